// round 11
// baseline (speedup 1.0000x reference)
#include <cuda_runtime.h>
#include <cuda_fp16.h>
#include <math.h>
#include <stdint.h>

#define DDIM 256
#define NROWS 8192
#define BM 128
#define BN 256
#define BK 32                     // fp16 per k-chunk
#define NITER (DDIM / BK)         // 8
#define NSTAGE 3
#define ROWB 80                   // 64B data + 16B pad (conflict-free ldmatrix)
#define A_BYTES (BM * ROWB)       // 10240
#define STAGE_BYTES ((BM + BN) * ROWB)    // 30720
#define SMEM_TOTAL (NSTAGE * STAGE_BYTES) // 92160 -> 2 CTAs/SM

// -------------------- scratch --------------------
__device__ __half g_Ah[NROWS * DDIM];   // x1 * sqrt(alpha), fp16
__device__ __half g_Bh[NROWS * DDIM];   // x2 * sqrt(alpha), fp16
__device__ float g_n1[NROWS];
__device__ float g_n2[NROWS];

// -------------------- helpers --------------------
__device__ __forceinline__ uint32_t smem_u32(const void* p) {
    uint32_t a;
    asm("{ .reg .u64 t; cvta.to.shared.u64 t, %1; cvt.u32.u64 %0, t; }" : "=r"(a) : "l"(p));
    return a;
}
__device__ __forceinline__ void cp_async16(uint32_t saddr, const void* g) {
    asm volatile("cp.async.cg.shared.global [%0], [%1], 16;" :: "r"(saddr), "l"(g));
}
__device__ __forceinline__ void ldmatrix_x4(uint32_t* r, uint32_t saddr) {
    asm volatile("ldmatrix.sync.aligned.m8n8.x4.shared.b16 {%0,%1,%2,%3}, [%4];"
                 : "=r"(r[0]), "=r"(r[1]), "=r"(r[2]), "=r"(r[3]) : "r"(saddr));
}
__device__ __forceinline__ void mma_f16(float* c, const uint32_t* a, const uint32_t* b) {
    asm("mma.sync.aligned.m16n8k16.row.col.f32.f16.f16.f32 "
        "{%0,%1,%2,%3}, {%4,%5,%6,%7}, {%8,%9}, {%0,%1,%2,%3};"
        : "+f"(c[0]), "+f"(c[1]), "+f"(c[2]), "+f"(c[3])
        : "r"(a[0]), "r"(a[1]), "r"(a[2]), "r"(a[3]), "r"(b[0]), "r"(b[1]));
}

// -------------------- prep: block-local softmax + scale + norms ------------
// 256 threads/block; block computes sqrt(softmax(alpha^2)) once in smem, then
// its 8 warps scale 8 rows. Warps [0, 8*gridDim.x) map to rows of x1 then x2.
__global__ void prep_kernel(const float* __restrict__ x1,
                            const float* __restrict__ x2,
                            const float* __restrict__ alpha_raw,
                            __half* __restrict__ Ah,
                            __half* __restrict__ Bh,
                            float* __restrict__ n1,
                            float* __restrict__ n2,
                            int N) {
    __shared__ float sh[DDIM];
    __shared__ float sas[DDIM];
    const int d = threadIdx.x;

    float t = alpha_raw[d] * alpha_raw[d];
    sh[d] = t;
    __syncthreads();
    #pragma unroll
    for (int s = 128; s > 0; s >>= 1) {
        if (d < s) sh[d] = fmaxf(sh[d], sh[d + s]);
        __syncthreads();
    }
    float mx = sh[0];
    __syncthreads();
    float e = expf(t - mx);
    sh[d] = e;
    __syncthreads();
    #pragma unroll
    for (int s = 128; s > 0; s >>= 1) {
        if (d < s) sh[d] += sh[d + s];
        __syncthreads();
    }
    sas[d] = sqrtf(e / sh[0]);
    __syncthreads();

    const int w = blockIdx.x * 8 + (threadIdx.x >> 5);
    const int lane = threadIdx.x & 31;
    const float* src;
    __half* dst;
    if (w < N) { src = x1 + (size_t)w * DDIM; dst = Ah + (size_t)w * DDIM; }
    else       { src = x2 + (size_t)(w - N) * DDIM; dst = Bh + (size_t)(w - N) * DDIM; }

    float s = 0.0f;
    #pragma unroll
    for (int j = 0; j < 2; j++) {
        const int c = j * 128 + lane * 4;
        float4 xv = *(const float4*)(src + c);
        float4 sv = *(const float4*)(sas + c);
        float v0 = xv.x * sv.x, v1 = xv.y * sv.y, v2 = xv.z * sv.z, v3 = xv.w * sv.w;
        __half h[4] = { __float2half(v0), __float2half(v1),
                        __float2half(v2), __float2half(v3) };
        *(uint2*)(dst + c) = *(const uint2*)h;
        s += v0 * v0 + v1 * v1 + v2 * v2 + v3 * v3;
    }
    #pragma unroll
    for (int o = 16; o > 0; o >>= 1)
        s += __shfl_xor_sync(0xFFFFFFFFu, s, o);
    if (lane == 0) {
        if (w < N) n1[w] = s;
        else       n2[w - N] = s;
    }
}

// -------------------- fused HMMA GEMM + RBF epilogue --------------------
// 256 threads (8 warps: 2 in M x 4 in N), warp tile 64x64, CTA tile 128x256.
__global__ void __launch_bounds__(256, 2)
rbf_mma_kernel(const __half* __restrict__ Ah,
               const __half* __restrict__ Bh,
               const float* __restrict__ n1,
               const float* __restrict__ n2,
               const float* __restrict__ variance_raw,
               float* __restrict__ out,
               int Mcols) {
    extern __shared__ char smem[];
    const uint32_t sbase = smem_u32(smem);
    const int tid = threadIdx.x;
    const int wid = tid >> 5;
    const int lane = tid & 31;
    const int wm = wid & 1;       // 2 warps in M, 64 rows each
    const int wn = wid >> 1;      // 4 warps in N, 64 cols each
    const int row0 = blockIdx.y * BM;
    const int col0 = blockIdx.x * BN;

    float acc[4][8][4];
    #pragma unroll
    for (int i = 0; i < 4; i++)
        #pragma unroll
        for (int j = 0; j < 8; j++)
            #pragma unroll
            for (int q = 0; q < 4; q++) acc[i][j][q] = 0.0f;

    // ---- per-thread load state: A 2 chunks, B 4 chunks (16B each) ----
    // per stage: A 128 rows x 4 chunks = 512; B 256 x 4 = 1024; /256 thr.
    const int r4 = tid >> 2;           // [0,64)
    const int c4 = tid & 3;            // [0,4)
    uint32_t aoff[2], boff[4];
    const __half *agp[2], *bgp[4];
    #pragma unroll
    for (int l = 0; l < 2; l++) {
        int r = r4 + l * 64;
        aoff[l] = (uint32_t)(r * ROWB + c4 * 16);
        agp[l] = Ah + (size_t)(row0 + r) * DDIM + c4 * 8;
    }
    #pragma unroll
    for (int l = 0; l < 4; l++) {
        int r = r4 + l * 64;
        boff[l] = (uint32_t)(r * ROWB + c4 * 16) + A_BYTES;
        bgp[l] = Bh + (size_t)(col0 + r) * DDIM + c4 * 8;
    }

    auto fill = [&](int ck) {
        const int kk = ck * BK;
        const uint32_t sb = sbase + (ck % NSTAGE) * STAGE_BYTES;
        #pragma unroll
        for (int l = 0; l < 2; l++)
            cp_async16(sb + aoff[l], agp[l] + kk);
        #pragma unroll
        for (int l = 0; l < 4; l++)
            cp_async16(sb + boff[l], bgp[l] + kk);
        asm volatile("cp.async.commit_group;" ::: "memory");
    };

    // ---- hoisted ldmatrix within-stage offsets ----
    const int lrow = lane & 15;
    const uint32_t lkb = (uint32_t)((lane >> 4) * 16);
    uint32_t afoff[4], bfoff[4];
    #pragma unroll
    for (int mt = 0; mt < 4; mt++)
        afoff[mt] = (uint32_t)((wm * 64 + mt * 16 + lrow) * ROWB) + lkb;
    #pragma unroll
    for (int t = 0; t < 4; t++)
        bfoff[t] = (uint32_t)((wn * 64 + t * 16 + lrow) * ROWB) + lkb + A_BYTES;

    fill(0); fill(1);

    // double-buffered fragments
    uint32_t af[2][4][4], bf[2][8][2];

#define LOAD_FRAGS(buf, koff)                                                  \
    do {                                                                       \
        _Pragma("unroll")                                                      \
        for (int mt = 0; mt < 4; mt++)                                         \
            ldmatrix_x4(af[buf][mt], (koff) + afoff[mt]);                      \
        _Pragma("unroll")                                                      \
        for (int t = 0; t < 4; t++) {                                          \
            uint32_t rr[4];                                                    \
            ldmatrix_x4(rr, (koff) + bfoff[t]);                                \
            bf[buf][t * 2][0] = rr[0]; bf[buf][t * 2][1] = rr[2];              \
            bf[buf][t * 2 + 1][0] = rr[1]; bf[buf][t * 2 + 1][1] = rr[3];      \
        }                                                                      \
    } while (0)

    #pragma unroll
    for (int i = 0; i < NITER; i++) {
        if (i < NITER - 1) asm volatile("cp.async.wait_group 1;" ::: "memory");
        else               asm volatile("cp.async.wait_group 0;" ::: "memory");
        __syncthreads();

        if (i + 2 < NITER) fill(i + 2);

        const uint32_t stb = sbase + (i % NSTAGE) * STAGE_BYTES;

        LOAD_FRAGS(0, stb);
        // 2 k-steps per chunk (BK=32)
        LOAD_FRAGS(1, stb + 32u);
        #pragma unroll
        for (int mt = 0; mt < 4; mt++)
            #pragma unroll
            for (int nt = 0; nt < 8; nt++)
                mma_f16(acc[mt][nt], af[0][mt], bf[0][nt]);
        #pragma unroll
        for (int mt = 0; mt < 4; mt++)
            #pragma unroll
            for (int nt = 0; nt < 8; nt++)
                mma_f16(acc[mt][nt], af[1][mt], bf[1][nt]);
    }
#undef LOAD_FRAGS

    // -------- epilogue --------
    const float vr = variance_raw[0];
    const float var = vr * vr;
    const int qrow = lane >> 2;
    const int qcol = (lane & 3) * 2;

    #pragma unroll
    for (int mt = 0; mt < 4; mt++) {
        const int rg = row0 + wm * 64 + mt * 16 + qrow;
        const float rnA = n1[rg];
        const float rnB = n1[rg + 8];
        #pragma unroll
        for (int nt = 0; nt < 8; nt++) {
            const int cg = col0 + wn * 64 + nt * 8 + qcol;
            float2 nn = *(const float2*)(n2 + cg);
            float sq0 = fmaxf(fmaf(-2.0f, acc[mt][nt][0], rnA + nn.x), 0.0f);
            float sq1 = fmaxf(fmaf(-2.0f, acc[mt][nt][1], rnA + nn.y), 0.0f);
            float sq2 = fmaxf(fmaf(-2.0f, acc[mt][nt][2], rnB + nn.x), 0.0f);
            float sq3 = fmaxf(fmaf(-2.0f, acc[mt][nt][3], rnB + nn.y), 0.0f);
            float2 v0 = make_float2(var * __expf(-0.5f * sq0), var * __expf(-0.5f * sq1));
            float2 v1 = make_float2(var * __expf(-0.5f * sq2), var * __expf(-0.5f * sq3));
            *(float2*)(out + (size_t)rg * Mcols + cg) = v0;
            *(float2*)(out + (size_t)(rg + 8) * Mcols + cg) = v1;
        }
    }
}

// -------------------- launch --------------------
extern "C" void kernel_launch(void* const* d_in, const int* in_sizes, int n_in,
                              void* d_out, int out_size) {
    const float* x1 = (const float*)d_in[0];
    const float* x2 = (const float*)d_in[1];
    const float* alpha_raw = (const float*)d_in[2];
    const float* variance_raw = (const float*)d_in[3];
    float* out = (float*)d_out;

    int N = in_sizes[0] / DDIM;
    int M = in_sizes[1] / DDIM;

    __half *Ah, *Bh;
    float *n1, *n2;
    cudaGetSymbolAddress((void**)&Ah, g_Ah);
    cudaGetSymbolAddress((void**)&Bh, g_Bh);
    cudaGetSymbolAddress((void**)&n1, g_n1);
    cudaGetSymbolAddress((void**)&n2, g_n2);

    cudaFuncSetAttribute(rbf_mma_kernel, cudaFuncAttributeMaxDynamicSharedMemorySize, SMEM_TOTAL);

    prep_kernel<<<(N + M) / 8, 256>>>(x1, x2, alpha_raw, Ah, Bh, n1, n2, N);

    dim3 grid(M / BN, N / BM);
    rbf_mma_kernel<<<grid, 256, SMEM_TOTAL>>>(Ah, Bh, n1, n2, variance_raw, out, M);
}

// round 13
// speedup vs baseline: 2.8803x; 2.8803x over previous
#include <cuda_runtime.h>
#include <cuda_fp16.h>
#include <math.h>
#include <stdint.h>

#define DDIM 256
#define NROWS 8192
#define BN 128                      // cols per CTA
#define BK 64                       // fp16 k per A chunk
#define ACH 16384                   // A stage bytes: 128 rows * 128B (swizzled)
#define SMB (3 * ACH)               // B region offset = 49152
#define BBYTES (BN * 512)           // B resident: 128 rows * 512B = 65536
#define SMEM_TOTAL (SMB + BBYTES)   // 114688 -> 2 CTAs/SM

// -------------------- scratch --------------------
__device__ __half g_Ah[NROWS * DDIM];   // x1 * sqrt(alpha), fp16
__device__ __half g_Bh[NROWS * DDIM];   // x2 * sqrt(alpha), fp16
__device__ float g_n1[NROWS];
__device__ float g_n2[NROWS];

// -------------------- helpers --------------------
__device__ __forceinline__ uint32_t smem_u32(const void* p) {
    uint32_t a;
    asm("{ .reg .u64 t; cvta.to.shared.u64 t, %1; cvt.u32.u64 %0, t; }" : "=r"(a) : "l"(p));
    return a;
}
__device__ __forceinline__ void cp_async16(uint32_t saddr, const void* g) {
    asm volatile("cp.async.cg.shared.global [%0], [%1], 16;" :: "r"(saddr), "l"(g));
}
__device__ __forceinline__ void ldmatrix_x4(uint32_t* r, uint32_t saddr) {
    asm volatile("ldmatrix.sync.aligned.m8n8.x4.shared.b16 {%0,%1,%2,%3}, [%4];"
                 : "=r"(r[0]), "=r"(r[1]), "=r"(r[2]), "=r"(r[3]) : "r"(saddr));
}
__device__ __forceinline__ void mma_f16(float* c, const uint32_t* a, const uint32_t* b) {
    asm("mma.sync.aligned.m16n8k16.row.col.f32.f16.f16.f32 "
        "{%0,%1,%2,%3}, {%4,%5,%6,%7}, {%8,%9}, {%0,%1,%2,%3};"
        : "+f"(c[0]), "+f"(c[1]), "+f"(c[2]), "+f"(c[3])
        : "r"(a[0]), "r"(a[1]), "r"(a[2]), "r"(a[3]), "r"(b[0]), "r"(b[1]));
}

// -------------------- prep: block-local softmax + scale + norms ------------
__global__ void prep_kernel(const float* __restrict__ x1,
                            const float* __restrict__ x2,
                            const float* __restrict__ alpha_raw,
                            __half* __restrict__ Ah,
                            __half* __restrict__ Bh,
                            float* __restrict__ n1,
                            float* __restrict__ n2,
                            int N) {
    __shared__ float sh[DDIM];
    __shared__ float sas[DDIM];
    const int d = threadIdx.x;

    float t = alpha_raw[d] * alpha_raw[d];
    sh[d] = t;
    __syncthreads();
    #pragma unroll
    for (int s = 128; s > 0; s >>= 1) {
        if (d < s) sh[d] = fmaxf(sh[d], sh[d + s]);
        __syncthreads();
    }
    float mx = sh[0];
    __syncthreads();
    float e = expf(t - mx);
    sh[d] = e;
    __syncthreads();
    #pragma unroll
    for (int s = 128; s > 0; s >>= 1) {
        if (d < s) sh[d] += sh[d + s];
        __syncthreads();
    }
    sas[d] = sqrtf(e / sh[0]);
    __syncthreads();

    const int w = blockIdx.x * 8 + (threadIdx.x >> 5);
    const int lane = threadIdx.x & 31;
    const float* src;
    __half* dst;
    if (w < N) { src = x1 + (size_t)w * DDIM; dst = Ah + (size_t)w * DDIM; }
    else       { src = x2 + (size_t)(w - N) * DDIM; dst = Bh + (size_t)(w - N) * DDIM; }

    float s = 0.0f;
    #pragma unroll
    for (int j = 0; j < 2; j++) {
        const int c = j * 128 + lane * 4;
        float4 xv = *(const float4*)(src + c);
        float4 sv = *(const float4*)(sas + c);
        float v0 = xv.x * sv.x, v1 = xv.y * sv.y, v2 = xv.z * sv.z, v3 = xv.w * sv.w;
        __half h[4] = { __float2half(v0), __float2half(v1),
                        __float2half(v2), __float2half(v3) };
        *(uint2*)(dst + c) = *(const uint2*)h;
        s += v0 * v0 + v1 * v1 + v2 * v2 + v3 * v3;
    }
    #pragma unroll
    for (int o = 16; o > 0; o >>= 1)
        s += __shfl_xor_sync(0xFFFFFFFFu, s, o);
    if (lane == 0) {
        if (w < N) n1[w] = s;
        else       n2[w - N] = s;
    }
}

// -------------------- fused HMMA GEMM + RBF epilogue --------------------
// 128 threads (4 warps, 2x2), warp tile 64x64. CTA output = 256x128 computed
// as two sequential 128x128 passes; B (128 x K=256 fp16, 64KB) stays resident
// in smem across both passes; A streams in 8 chunks through a 3-stage ring.
// XOR swizzle (chunk ^ (row&7)) in both layouts; fill leads compute by 2.
__global__ void __launch_bounds__(128, 2)
rbf_mma_kernel(const __half* __restrict__ Ah,
               const __half* __restrict__ Bh,
               const float* __restrict__ n1,
               const float* __restrict__ n2,
               const float* __restrict__ variance_raw,
               float* __restrict__ out,
               int Mcols) {
    extern __shared__ char smem[];
    const uint32_t sbase = smem_u32(smem);
    const int tid = threadIdx.x;
    const int wid = tid >> 5;
    const int lane = tid & 31;
    const int wm = wid & 1;       // 2 warps in M, 64 rows each (per pass)
    const int wn = wid >> 1;      // 2 warps in N, 64 cols each
    const int row0 = blockIdx.y * 256;
    const int col0 = blockIdx.x * BN;

    float acc[4][8][4];
    #pragma unroll
    for (int i = 0; i < 4; i++)
        #pragma unroll
        for (int j = 0; j < 8; j++)
            #pragma unroll
            for (int q = 0; q < 4; q++) acc[i][j][q] = 0.0f;

    // ---- A fill geometry: 1024 16B-chunks per stage / 128 thr = 8 each ----
    uint32_t soffA[8], goffA[8];
    #pragma unroll
    for (int l = 0; l < 8; l++) {
        int u = tid + l * 128;
        int r = u >> 3, c = u & 7;
        soffA[l] = (uint32_t)(r * 128 + ((c ^ (r & 7)) << 4));
        goffA[l] = (uint32_t)(r * DDIM + c * 8);    // element offset
    }
    const __half* abase = Ah + (size_t)row0 * DDIM;

    // ---- B fill (once): warp covers rows wid+4l, lane = 16B chunk ----
    const __half* bsrc = Bh + (size_t)(col0 + wid) * DDIM + lane * 8;
    const uint32_t bcol0 = (uint32_t)((lane ^ wid) << 4);
    #pragma unroll
    for (int l = 0; l < 32; l++) {
        const int r = wid + l * 4;
        const uint32_t col = (l & 1) ? (bcol0 ^ 64u) : bcol0;
        cp_async16(sbase + SMB + (uint32_t)(r * 512) + col,
                   bsrc + (size_t)l * 4 * DDIM);
    }

#define FILLA(j) do {                                                          \
        const uint32_t stb_ = sbase + ((j) % 3) * ACH;                         \
        const size_t go_ = (size_t)((j) >> 2) * 128 * DDIM + ((j) & 3) * BK;   \
        _Pragma("unroll")                                                      \
        for (int l = 0; l < 8; l++)                                            \
            cp_async16(stb_ + soffA[l], abase + goffA[l] + go_);               \
        asm volatile("cp.async.commit_group;" ::: "memory");                   \
    } while (0)

    FILLA(0);            // group 0 = B + A0
    FILLA(1);            // group 1 = A1

    // ---- ldmatrix bases ----
    const int lrow = lane & 15;
    const int hb = lane >> 4;
    const uint32_t s74 = (uint32_t)((lrow & 7) << 4);
    uint32_t arow[4], brow[4];
    #pragma unroll
    for (int mt = 0; mt < 4; mt++)
        arow[mt] = (uint32_t)((wm * 64 + mt * 16 + lrow) * 128);
    #pragma unroll
    for (int t = 0; t < 4; t++)
        brow[t] = sbase + SMB + (uint32_t)((wn * 64 + t * 16 + lrow) * 512);  // FIX: +sbase

    uint32_t af[2][4][4], bf[2][8][2];

#define LOAD_FRAGS(buf, stb, jk, ks) do {                                      \
        const uint32_t ac_ = ((uint32_t)(((ks) * 2 + hb) << 4)) ^ s74;         \
        const uint32_t bc_ = ((uint32_t)((((jk) * 8) + (ks) * 2 + hb) << 4)) ^ s74; \
        _Pragma("unroll")                                                      \
        for (int mt = 0; mt < 4; mt++)                                         \
            ldmatrix_x4(af[buf][mt], (stb) + arow[mt] + ac_);                  \
        _Pragma("unroll")                                                      \
        for (int t = 0; t < 4; t++) {                                          \
            uint32_t rr[4];                                                    \
            ldmatrix_x4(rr, brow[t] + bc_);                                    \
            bf[buf][t * 2][0] = rr[0]; bf[buf][t * 2][1] = rr[2];              \
            bf[buf][t * 2 + 1][0] = rr[1]; bf[buf][t * 2 + 1][1] = rr[3];      \
        }                                                                      \
    } while (0)

    const float vr = variance_raw[0];
    const float var = vr * vr;
    const int qrow = lane >> 2;
    const int qcol = (lane & 3) * 2;

#define EPILOGUE(prow) do {                                                    \
        _Pragma("unroll")                                                      \
        for (int mt = 0; mt < 4; mt++) {                                       \
            const int rg = (prow) + wm * 64 + mt * 16 + qrow;                  \
            const float rnA = n1[rg];                                          \
            const float rnB = n1[rg + 8];                                      \
            _Pragma("unroll")                                                  \
            for (int nt = 0; nt < 8; nt++) {                                   \
                const int cg = col0 + wn * 64 + nt * 8 + qcol;                 \
                float2 nn = *(const float2*)(n2 + cg);                         \
                float sq0 = fmaxf(fmaf(-2.0f, acc[mt][nt][0], rnA + nn.x), 0.0f); \
                float sq1 = fmaxf(fmaf(-2.0f, acc[mt][nt][1], rnA + nn.y), 0.0f); \
                float sq2 = fmaxf(fmaf(-2.0f, acc[mt][nt][2], rnB + nn.x), 0.0f); \
                float sq3 = fmaxf(fmaf(-2.0f, acc[mt][nt][3], rnB + nn.y), 0.0f); \
                float2 v0 = make_float2(var * __expf(-0.5f * sq0),             \
                                        var * __expf(-0.5f * sq1));            \
                float2 v1 = make_float2(var * __expf(-0.5f * sq2),             \
                                        var * __expf(-0.5f * sq3));            \
                *(float2*)(out + (size_t)rg * Mcols + cg) = v0;                \
                *(float2*)(out + (size_t)(rg + 8) * Mcols + cg) = v1;          \
                acc[mt][nt][0] = 0.0f; acc[mt][nt][1] = 0.0f;                  \
                acc[mt][nt][2] = 0.0f; acc[mt][nt][3] = 0.0f;                  \
            }                                                                  \
        }                                                                      \
    } while (0)

    #pragma unroll
    for (int j = 0; j < 8; j++) {
        if (j < 7) asm volatile("cp.async.wait_group 1;" ::: "memory");
        else       asm volatile("cp.async.wait_group 0;" ::: "memory");
        __syncthreads();

        if (j + 2 < 8) FILLA(j + 2);

        const uint32_t stb = sbase + (j % 3) * ACH;
        const int jk = j & 3;

        LOAD_FRAGS(0, stb, jk, 0);
        #pragma unroll
        for (int ks = 0; ks < 4; ks++) {
            if (ks < 3) LOAD_FRAGS((ks + 1) & 1, stb, jk, ks + 1);
            const int cb = ks & 1;
            #pragma unroll
            for (int mt = 0; mt < 4; mt++)
                #pragma unroll
                for (int nt = 0; nt < 8; nt++)
                    mma_f16(acc[mt][nt], af[cb][mt], bf[cb][nt]);
        }

        if (j == 3) {
            // pass-0 epilogue: overlaps in-flight A chunks 4,5 for pass 1
            EPILOGUE(row0);
        }
    }
    EPILOGUE(row0 + 128);

#undef FILLA
#undef LOAD_FRAGS
#undef EPILOGUE
}

// -------------------- launch --------------------
extern "C" void kernel_launch(void* const* d_in, const int* in_sizes, int n_in,
                              void* d_out, int out_size) {
    const float* x1 = (const float*)d_in[0];
    const float* x2 = (const float*)d_in[1];
    const float* alpha_raw = (const float*)d_in[2];
    const float* variance_raw = (const float*)d_in[3];
    float* out = (float*)d_out;

    int N = in_sizes[0] / DDIM;
    int M = in_sizes[1] / DDIM;

    __half *Ah, *Bh;
    float *n1, *n2;
    cudaGetSymbolAddress((void**)&Ah, g_Ah);
    cudaGetSymbolAddress((void**)&Bh, g_Bh);
    cudaGetSymbolAddress((void**)&n1, g_n1);
    cudaGetSymbolAddress((void**)&n2, g_n2);

    cudaFuncSetAttribute(rbf_mma_kernel, cudaFuncAttributeMaxDynamicSharedMemorySize, SMEM_TOTAL);

    prep_kernel<<<(N + M) / 8, 256>>>(x1, x2, alpha_raw, Ah, Bh, n1, n2, N);

    dim3 grid(M / BN, N / 256);
    rbf_mma_kernel<<<grid, 128, SMEM_TOTAL>>>(Ah, Bh, n1, n2, variance_raw, out, M);
}